// round 16
// baseline (speedup 1.0000x reference)
#include <cuda_runtime.h>

// Bidirectional LSTM, H=39, B=512, T=2048, fp32 — two-phase.
// Phase 1 (pre_kernel): pre[d][b][t][row] = s_row * (W_ih[row,:]·x[b,t,:] + b_ih+b_hh),
//   s_row = 2 for tanh rows (78..116). Thread owns rows (2r, 2r+1) -> STG.64.
// Phase 2 (lstm_rec_kernel): 2 warps per sequence, 512 blocks x 64 threads.
//   Warp w owns gate rows 78w..78w+77; lane l holds rows 78w+32s+l (s=0..2)
//   -> <=120 weight regs/thread (R14's 1-warp version spilled at 252 regs).
//   Gate exchange via 156-float smem + __syncthreads (nw=2, ~7 cyc floor).
//   Cells owned by tid<39. Pre prefetched 2 steps deep (in-bounds by
//   construction: row offsets clamped <=155; bwd seqs over-read downward,
//   fwd seqs into the adjacent region).

#define H        39
#define G4       156
#define T_STEPS  2048
#define B_TOT    512
#define THREADS  160
#define PADW     40
#define TCH      64
#define TBLK     128
#define NBLKT    (T_STEPS / TBLK)   // 16

// 2 * 512 * 2048 * 156 floats = 1.31 GB scratch (bss)
__device__ float g_pre[2ULL * B_TOT * T_STEPS * G4];

union F2U { float2 f; unsigned long long u; };

__device__ __forceinline__ float2 ffma2(float2 a, float2 b, float2 c) {
    F2U A, B, C, D;
    A.f = a; B.f = b; C.f = c;
    asm("fma.rn.f32x2 %0, %1, %2, %3;" : "=l"(D.u) : "l"(A.u), "l"(B.u), "l"(C.u));
    return D.f;
}

// ---------------------------------------------------------------------------
// Phase 1. grid = 2*512*16 blocks x 160 thr. Subgroup tid/80 owns 64 tt of a
// 128-tt staged x tile; thread r (<78) owns rows 2r, 2r+1 (80 weight regs),
// paired rows -> one STG.64 per tt.
// ---------------------------------------------------------------------------
__global__ __launch_bounds__(THREADS) void pre_kernel(
    const float* __restrict__ x,
    const float* __restrict__ Wih_f, const float* __restrict__ bih_f,
    const float* __restrict__ bhh_f,
    const float* __restrict__ Wih_b, const float* __restrict__ bih_b,
    const float* __restrict__ bhh_b)
{
    __shared__ __align__(16) float sxt[TBLK][PADW];

    const int tid = threadIdx.x;
    const int bx  = blockIdx.x;
    const int tb  = bx & (NBLKT - 1);
    const int bb  = (bx >> 4) & (B_TOT - 1);
    const int d   = bx >> 13;

    const float* Wih = d ? Wih_b : Wih_f;
    const float* bih = d ? bih_b : bih_f;
    const float* bhh = d ? bhh_b : bhh_f;

    const float* xb = x + ((size_t)bb * T_STEPS + (size_t)tb * TBLK) * H;
    for (int idx = tid; idx < TBLK * H; idx += THREADS) {
        const int t = idx / H;
        const int k = idx - t * H;
        sxt[t][k] = xb[idx];
    }
    for (int t = tid; t < TBLK; t += THREADS) sxt[t][H] = 0.0f;

    const int sub = (tid >= 80) ? 1 : 0;
    const int r   = tid - 80 * sub;
    const bool valid = (r < 78);
    const int rr = valid ? r : 77;
    const int r0 = 2 * rr;
    const int r1 = 2 * rr + 1;

    float2 w0[20], w1[20];
    #pragma unroll
    for (int k = 0; k < 20; k++) {
        const int i0 = 2 * k, i1 = i0 + 1;
        const float a0 = Wih[r0 * H + i0];
        const float a1 = (i1 < H) ? Wih[r0 * H + i1] : 0.0f;
        const float b0 = Wih[r1 * H + i0];
        const float b1 = (i1 < H) ? Wih[r1 * H + i1] : 0.0f;
        w0[k] = make_float2(a0, a1);
        w1[k] = make_float2(b0, b1);
    }
    const float bias0 = bih[r0] + bhh[r0];
    const float bias1 = bih[r1] + bhh[r1];
    // fold tanh input scale for g rows (78..116)
    const float sc0 = (r0 >= 2 * H && r0 < 3 * H) ? 2.0f : 1.0f;
    const float sc1 = (r1 >= 2 * H && r1 < 3 * H) ? 2.0f : 1.0f;

    __syncthreads();

    const float (*tile)[PADW] = &sxt[sub * TCH];
    float* po = g_pre + (((size_t)d * B_TOT + bb) * T_STEPS
                         + (size_t)tb * TBLK + (size_t)sub * TCH) * G4 + r0;

    #pragma unroll 2
    for (int tt = 0; tt < TCH; tt++) {
        const float4* x4 = reinterpret_cast<const float4*>(tile[tt]);
        float2 acc0 = make_float2(0.f, 0.f);
        float2 acc1 = make_float2(0.f, 0.f);
        #pragma unroll
        for (int k = 0; k < 10; k++) {
            const float4 xv = x4[k];
            const float2 lo = make_float2(xv.x, xv.y);
            const float2 hi = make_float2(xv.z, xv.w);
            acc0 = ffma2(w0[2 * k],     lo, acc0);
            acc0 = ffma2(w0[2 * k + 1], hi, acc0);
            acc1 = ffma2(w1[2 * k],     lo, acc1);
            acc1 = ffma2(w1[2 * k + 1], hi, acc1);
        }
        if (valid) {
            float2 v;
            v.x = sc0 * (bias0 + acc0.x + acc0.y);
            v.y = sc1 * (bias1 + acc1.x + acc1.y);
            *reinterpret_cast<float2*>(po + (size_t)tt * G4) = v;
        }
    }
}

// ---------------------------------------------------------------------------
// Phase 2: recurrence. 512 blocks x 64 threads (2 warps per sequence).
// ---------------------------------------------------------------------------
__global__ __launch_bounds__(64) void lstm_rec_kernel(
    const float* __restrict__ Whh_f, const float* __restrict__ Whh_b,
    float* __restrict__ out)
{
    __shared__ __align__(16) float sh_h[PADW];   // h (pad elem 39 stays 0)
    __shared__ float sg[G4 + 4];                 // activated gates by row

    const int tid = threadIdx.x;
    const int l   = tid & 31;
    const int wpw = tid >> 5;                    // warp id 0/1
    const int bx  = blockIdx.x;
    const int dir = bx >> 9;
    const int bb  = bx & (B_TOT - 1);

    const float* Whh = dir ? Whh_b : Whh_f;

    // ---- weights: warp w owns rows 78w + 32s + l (s=0..2, valid 32s+l<78) ----
    float2 w2[3][20];
    float ka[3];
    int   rofs[3];            // clamped pre-read row offset per slot
    #pragma unroll
    for (int s = 0; s < 3; s++) {
        const int rl = 32 * s + l;           // row within warp's 78
        const bool ok = (rl < 78);
        const int r  = 78 * wpw + (ok ? rl : l);   // clamped row <= 109
        rofs[s] = r;
        const bool isg = (r >= 2 * H) && (r < 3 * H);
        const float ws = ok ? (isg ? 2.0f : 1.0f) : 0.0f;
        ka[s] = isg ? 2.0f : 1.0f;
        #pragma unroll
        for (int k = 0; k < 20; k++) {
            const int i0 = 2 * k, i1 = i0 + 1;
            const float a = Whh[r * H + i0] * ws;
            const float b = (i1 < H) ? Whh[r * H + i1] * ws : 0.0f;
            w2[s][k] = make_float2(a, b);
        }
    }

    // ---- init smem ----
    if (tid < PADW) sh_h[tid] = 0.0f;

    // ---- pre pointer + 2-deep prefetch ----
    // In-bounds: row offsets <= 155; dir=1 over-reads go to lower addresses,
    // dir=0 over-reads land in the following (dir,b) region; garbage values
    // are rotated in but never consumed for t >= T_STEPS.
    const long pstep = dir ? -(long)G4 : (long)G4;
    const float* q = g_pre
        + ((size_t)dir * B_TOT + bb) * ((size_t)T_STEPS * G4)
        + (dir ? (size_t)(T_STEPS - 1) * G4 : 0);
    float pa[3], pb[3];
    #pragma unroll
    for (int s = 0; s < 3; s++) pa[s] = __ldg(q + rofs[s]);
    q += pstep;
    #pragma unroll
    for (int s = 0; s < 3; s++) pb[s] = __ldg(q + rofs[s]);
    q += pstep;

    const bool cown = (tid < H);
    float* op = out + (size_t)bb * (T_STEPS * 2 * H) + dir * H + (cown ? tid : 0);
    float c = 0.0f;

    __syncthreads();

    #pragma unroll 1
    for (int t = 0; t < T_STEPS; t++) {
        // prefetch pre for t+2
        float pn[3];
        #pragma unroll
        for (int s = 0; s < 3; s++) pn[s] = __ldg(q + rofs[s]);
        q += pstep;

        // ---- matvec: 3 rows/lane, h broadcast via uniform LDS.128 ----
        float2 acc[3];
        #pragma unroll
        for (int s = 0; s < 3; s++) acc[s] = make_float2(0.f, 0.f);
        const float4* h4 = reinterpret_cast<const float4*>(sh_h);
        #pragma unroll
        for (int k = 0; k < 10; k++) {
            const float4 hv = h4[k];
            const float2 lo = make_float2(hv.x, hv.y);
            const float2 hi = make_float2(hv.z, hv.w);
            #pragma unroll
            for (int s = 0; s < 3; s++) {
                acc[s] = ffma2(w2[s][2 * k],     lo, acc[s]);
                acc[s] = ffma2(w2[s][2 * k + 1], hi, acc[s]);
            }
        }

        // ---- unified activation: y = fma(ka, 1/(1+e^-p) - 1, 1) ----
        #pragma unroll
        for (int s = 0; s < 3; s++) {
            const float p = pa[s] + acc[s].x + acc[s].y;
            const float e = __expf(-p);
            const float u = __fdividef(1.0f, 1.0f + e);
            const float y = fmaf(ka[s], u - 1.0f, 1.0f);
            if (32 * s + l < 78) sg[rofs[s]] = y;
        }
        __syncthreads();

        // ---- cell update: thread tid (<39) owns cell tid ----
        if (cown) {
            const float gi = sg[tid];
            const float gf = sg[H + tid];
            const float gg = sg[2 * H + tid];
            const float go = sg[3 * H + tid];
            c = fmaf(gf, c, gi * gg);
            const float e2 = __expf(c + c);
            const float th = 1.0f - 2.0f * __fdividef(1.0f, e2 + 1.0f);
            const float h = go * th;
            sh_h[tid] = h;
            *op = h;
        }
        op += 2 * H;
        __syncthreads();

        #pragma unroll
        for (int s = 0; s < 3; s++) { pa[s] = pb[s]; pb[s] = pn[s]; }
    }
}

extern "C" void kernel_launch(void* const* d_in, const int* in_sizes, int n_in,
                              void* d_out, int out_size) {
    const float* x     = (const float*)d_in[0];
    const float* Wih_f = (const float*)d_in[1];
    const float* Whh_f = (const float*)d_in[2];
    const float* bih_f = (const float*)d_in[3];
    const float* bhh_f = (const float*)d_in[4];
    const float* Wih_b = (const float*)d_in[5];
    const float* Whh_b = (const float*)d_in[6];
    const float* bih_b = (const float*)d_in[7];
    const float* bhh_b = (const float*)d_in[8];
    float* out = (float*)d_out;

    pre_kernel<<<2 * B_TOT * NBLKT, THREADS>>>(x, Wih_f, bih_f, bhh_f,
                                               Wih_b, bih_b, bhh_b);
    lstm_rec_kernel<<<2 * B_TOT, 64>>>(Whh_f, Whh_b, out);
}

// round 17
// speedup vs baseline: 1.0334x; 1.0334x over previous
#include <cuda_runtime.h>

// Bidirectional LSTM, H=39, B=512, T=2048, fp32 — two-phase.
// Phase 1 (pre_kernel): pre[d][b][t][row] = s_row*(W_ih[row,:]·x[b,t,:]+b_ih+b_hh),
//   s_row = 2 for tanh rows (78..116) — folds the tanh input scale.
// Phase 2 (lstm_rec_kernel): 128 blocks x 128 threads. Each of the 4 warps is
//   INDEPENDENT (no __syncthreads) and owns TWO same-direction sequences,
//   sharing one register copy of W_hh (200 regs). Two sequences give two
//   independent FFMA2 chains per slot -> latency self-hidden; 4 warps/block
//   guarantee all 4 SMSPs are fed even under the wid%4 mapping (R14's
//   single-warp blocks risked piling every warp onto SMSP 0).
//   Exchange via per-warp smem + __syncwarp only. 1-step pre prefetch
//   (row offsets clamped <=155; over-reads stay inside g_pre).

#define H        39
#define G4       156
#define T_STEPS  2048
#define B_TOT    512
#define THREADS  160
#define PADW     40
#define TCH      64
#define TBLK     128
#define NBLKT    (T_STEPS / TBLK)   // 16

// 2 * 512 * 2048 * 156 floats = 1.31 GB scratch (bss)
__device__ float g_pre[2ULL * B_TOT * T_STEPS * G4];

union F2U { float2 f; unsigned long long u; };

__device__ __forceinline__ float2 ffma2(float2 a, float2 b, float2 c) {
    F2U A, B, C, D;
    A.f = a; B.f = b; C.f = c;
    asm("fma.rn.f32x2 %0, %1, %2, %3;" : "=l"(D.u) : "l"(A.u), "l"(B.u), "l"(C.u));
    return D.f;
}

// ---------------------------------------------------------------------------
// Phase 1. grid = 2*512*16 blocks x 160 thr. Subgroup tid/80 owns 64 tt of a
// 128-tt staged x tile; thread r (<78) owns rows 2r, 2r+1 -> one STG.64/tt.
// ---------------------------------------------------------------------------
__global__ __launch_bounds__(THREADS) void pre_kernel(
    const float* __restrict__ x,
    const float* __restrict__ Wih_f, const float* __restrict__ bih_f,
    const float* __restrict__ bhh_f,
    const float* __restrict__ Wih_b, const float* __restrict__ bih_b,
    const float* __restrict__ bhh_b)
{
    __shared__ __align__(16) float sxt[TBLK][PADW];

    const int tid = threadIdx.x;
    const int bx  = blockIdx.x;
    const int tb  = bx & (NBLKT - 1);
    const int bb  = (bx >> 4) & (B_TOT - 1);
    const int d   = bx >> 13;

    const float* Wih = d ? Wih_b : Wih_f;
    const float* bih = d ? bih_b : bih_f;
    const float* bhh = d ? bhh_b : bhh_f;

    const float* xb = x + ((size_t)bb * T_STEPS + (size_t)tb * TBLK) * H;
    for (int idx = tid; idx < TBLK * H; idx += THREADS) {
        const int t = idx / H;
        const int k = idx - t * H;
        sxt[t][k] = xb[idx];
    }
    for (int t = tid; t < TBLK; t += THREADS) sxt[t][H] = 0.0f;

    const int sub = (tid >= 80) ? 1 : 0;
    const int r   = tid - 80 * sub;
    const bool valid = (r < 78);
    const int rr = valid ? r : 77;
    const int r0 = 2 * rr;
    const int r1 = 2 * rr + 1;

    float2 w0[20], w1[20];
    #pragma unroll
    for (int k = 0; k < 20; k++) {
        const int i0 = 2 * k, i1 = i0 + 1;
        const float a0 = Wih[r0 * H + i0];
        const float a1 = (i1 < H) ? Wih[r0 * H + i1] : 0.0f;
        const float b0 = Wih[r1 * H + i0];
        const float b1 = (i1 < H) ? Wih[r1 * H + i1] : 0.0f;
        w0[k] = make_float2(a0, a1);
        w1[k] = make_float2(b0, b1);
    }
    const float bias0 = bih[r0] + bhh[r0];
    const float bias1 = bih[r1] + bhh[r1];
    const float sc0 = (r0 >= 2 * H && r0 < 3 * H) ? 2.0f : 1.0f;
    const float sc1 = (r1 >= 2 * H && r1 < 3 * H) ? 2.0f : 1.0f;

    __syncthreads();

    const float (*tile)[PADW] = &sxt[sub * TCH];
    float* po = g_pre + (((size_t)d * B_TOT + bb) * T_STEPS
                         + (size_t)tb * TBLK + (size_t)sub * TCH) * G4 + r0;

    #pragma unroll 2
    for (int tt = 0; tt < TCH; tt++) {
        const float4* x4 = reinterpret_cast<const float4*>(tile[tt]);
        float2 acc0 = make_float2(0.f, 0.f);
        float2 acc1 = make_float2(0.f, 0.f);
        #pragma unroll
        for (int k = 0; k < 10; k++) {
            const float4 xv = x4[k];
            const float2 lo = make_float2(xv.x, xv.y);
            const float2 hi = make_float2(xv.z, xv.w);
            acc0 = ffma2(w0[2 * k],     lo, acc0);
            acc0 = ffma2(w0[2 * k + 1], hi, acc0);
            acc1 = ffma2(w1[2 * k],     lo, acc1);
            acc1 = ffma2(w1[2 * k + 1], hi, acc1);
        }
        if (valid) {
            float2 v;
            v.x = sc0 * (bias0 + acc0.x + acc0.y);
            v.y = sc1 * (bias1 + acc1.x + acc1.y);
            *reinterpret_cast<float2*>(po + (size_t)tt * G4) = v;
        }
    }
}

// ---------------------------------------------------------------------------
// Phase 2: recurrence. 128 blocks x 128 threads; warp = 2 sequences.
// ---------------------------------------------------------------------------
struct WarpSmem {
    float sh0[PADW];        // h of seq 0 (pad elem 39 stays 0)
    float sh1[PADW];        // h of seq 1
    float sg0[G4 + 4];      // activated gates, seq 0
    float sg1[G4 + 4];      // activated gates, seq 1
};

__global__ __launch_bounds__(128, 1) void lstm_rec_kernel(
    const float* __restrict__ Whh_f, const float* __restrict__ Whh_b,
    float* __restrict__ out)
{
    __shared__ __align__(16) WarpSmem ws[4];

    const int tid = threadIdx.x;
    const int l   = tid & 31;
    const int wpd = tid >> 5;                 // warp 0..3
    WarpSmem& W   = ws[wpd];

    const int gseq = blockIdx.x * 8 + wpd * 2;   // 0..1022, pair same dir
    const int dir  = gseq >> 9;
    const int bb0  = gseq & (B_TOT - 1);

    const float* Whh = dir ? Whh_b : Whh_f;

    // ---- weights: slot s -> row 32s + l (clamped); g rows prescaled x2 ----
    float2 w2[5][20];
    float ka[5];
    int   rofs[5];
    #pragma unroll
    for (int s = 0; s < 5; s++) {
        const int r0 = 32 * s + l;
        const bool ok = (r0 < G4);
        const int r = ok ? r0 : l;            // clamp: re-read row l, discard
        rofs[s] = r;
        const bool isg = (r >= 2 * H) && (r < 3 * H);
        const float wsc = ok ? (isg ? 2.0f : 1.0f) : 0.0f;
        ka[s] = isg ? 2.0f : 1.0f;
        #pragma unroll
        for (int k = 0; k < 20; k++) {
            const int i0 = 2 * k, i1 = i0 + 1;
            const float a = Whh[r * H + i0] * wsc;
            const float b = (i1 < H) ? Whh[r * H + i1] * wsc : 0.0f;
            w2[s][k] = make_float2(a, b);
        }
    }

    // ---- init smem h = 0 ----
    W.sh0[l] = 0.0f;  W.sh1[l] = 0.0f;
    if (l < 8) { W.sh0[32 + l] = 0.0f; W.sh1[32 + l] = 0.0f; }

    // ---- pre pointers + 1-step prefetch (over-reads stay inside g_pre) ----
    const long pstep = dir ? -(long)G4 : (long)G4;
    const float* q0 = g_pre
        + ((size_t)dir * B_TOT + bb0) * ((size_t)T_STEPS * G4)
        + (dir ? (size_t)(T_STEPS - 1) * G4 : 0);
    const float* q1 = q0 + (size_t)T_STEPS * G4;   // seq bb0+1, same dir
    float pc0[5], pc1[5];
    #pragma unroll
    for (int s = 0; s < 5; s++) { pc0[s] = __ldg(q0 + rofs[s]); pc1[s] = __ldg(q1 + rofs[s]); }
    q0 += pstep;  q1 += pstep;

    const size_t oseq = (size_t)T_STEPS * 2 * H;
    float* op0 = out + (size_t)bb0 * oseq + dir * H;
    float* op1 = op0 + oseq;

    float c00 = 0.f, c01 = 0.f, c10 = 0.f, c11 = 0.f;
    __syncwarp();

    #pragma unroll 1
    for (int t = 0; t < T_STEPS; t++) {
        // prefetch pre for t+1
        float pn0[5], pn1[5];
        #pragma unroll
        for (int s = 0; s < 5; s++) { pn0[s] = __ldg(q0 + rofs[s]); pn1[s] = __ldg(q1 + rofs[s]); }
        q0 += pstep;  q1 += pstep;

        // ---- dual matvec: 5 rows/lane x 2 seqs, h broadcast LDS.128 ----
        float2 a0[5], a1[5];
        #pragma unroll
        for (int s = 0; s < 5; s++) { a0[s] = make_float2(0.f, 0.f); a1[s] = make_float2(0.f, 0.f); }
        const float4* h40 = reinterpret_cast<const float4*>(W.sh0);
        const float4* h41 = reinterpret_cast<const float4*>(W.sh1);
        #pragma unroll
        for (int k = 0; k < 10; k++) {
            const float4 hv0 = h40[k];
            const float4 hv1 = h41[k];
            const float2 lo0 = make_float2(hv0.x, hv0.y);
            const float2 hi0 = make_float2(hv0.z, hv0.w);
            const float2 lo1 = make_float2(hv1.x, hv1.y);
            const float2 hi1 = make_float2(hv1.z, hv1.w);
            #pragma unroll
            for (int s = 0; s < 5; s++) {
                a0[s] = ffma2(w2[s][2 * k],     lo0, a0[s]);
                a0[s] = ffma2(w2[s][2 * k + 1], hi0, a0[s]);
                a1[s] = ffma2(w2[s][2 * k],     lo1, a1[s]);
                a1[s] = ffma2(w2[s][2 * k + 1], hi1, a1[s]);
            }
        }

        // ---- activations: y = fma(ka, 1/(1+e^-p) - 1, 1) ----
        #pragma unroll
        for (int s = 0; s < 5; s++) {
            const bool ok = (32 * s + l < G4);
            const float p0 = pc0[s] + a0[s].x + a0[s].y;
            const float e0 = __expf(-p0);
            const float u0 = __fdividef(1.0f, 1.0f + e0);
            const float y0 = fmaf(ka[s], u0 - 1.0f, 1.0f);
            const float p1 = pc1[s] + a1[s].x + a1[s].y;
            const float e1 = __expf(-p1);
            const float u1 = __fdividef(1.0f, 1.0f + e1);
            const float y1 = fmaf(ka[s], u1 - 1.0f, 1.0f);
            if (ok) { W.sg0[rofs[s]] = y0; W.sg1[rofs[s]] = y1; }
        }
        __syncwarp();

        // ---- cell updates: lane l owns cell l (both seqs); l<7 also 32+l ----
        {
            const float gi = W.sg0[l], gf = W.sg0[H + l];
            const float gg = W.sg0[2 * H + l], go = W.sg0[3 * H + l];
            c00 = fmaf(gf, c00, gi * gg);
            const float e2 = __expf(c00 + c00);
            const float th = 1.0f - 2.0f * __fdividef(1.0f, e2 + 1.0f);
            const float h = go * th;
            W.sh0[l] = h;  op0[l] = h;
        }
        {
            const float gi = W.sg1[l], gf = W.sg1[H + l];
            const float gg = W.sg1[2 * H + l], go = W.sg1[3 * H + l];
            c10 = fmaf(gf, c10, gi * gg);
            const float e2 = __expf(c10 + c10);
            const float th = 1.0f - 2.0f * __fdividef(1.0f, e2 + 1.0f);
            const float h = go * th;
            W.sh1[l] = h;  op1[l] = h;
        }
        if (l < 7) {
            const int j = 32 + l;
            {
                const float gi = W.sg0[j], gf = W.sg0[H + j];
                const float gg = W.sg0[2 * H + j], go = W.sg0[3 * H + j];
                c01 = fmaf(gf, c01, gi * gg);
                const float e2 = __expf(c01 + c01);
                const float th = 1.0f - 2.0f * __fdividef(1.0f, e2 + 1.0f);
                const float h = go * th;
                W.sh0[j] = h;  op0[j] = h;
            }
            {
                const float gi = W.sg1[j], gf = W.sg1[H + j];
                const float gg = W.sg1[2 * H + j], go = W.sg1[3 * H + j];
                c11 = fmaf(gf, c11, gi * gg);
                const float e2 = __expf(c11 + c11);
                const float th = 1.0f - 2.0f * __fdividef(1.0f, e2 + 1.0f);
                const float h = go * th;
                W.sh1[j] = h;  op1[j] = h;
            }
        }
        __syncwarp();

        op0 += 2 * H;  op1 += 2 * H;
        #pragma unroll
        for (int s = 0; s < 5; s++) { pc0[s] = pn0[s]; pc1[s] = pn1[s]; }
    }
}

extern "C" void kernel_launch(void* const* d_in, const int* in_sizes, int n_in,
                              void* d_out, int out_size) {
    const float* x     = (const float*)d_in[0];
    const float* Wih_f = (const float*)d_in[1];
    const float* Whh_f = (const float*)d_in[2];
    const float* bih_f = (const float*)d_in[3];
    const float* bhh_f = (const float*)d_in[4];
    const float* Wih_b = (const float*)d_in[5];
    const float* Whh_b = (const float*)d_in[6];
    const float* bih_b = (const float*)d_in[7];
    const float* bhh_b = (const float*)d_in[8];
    float* out = (float*)d_out;

    pre_kernel<<<2 * B_TOT * NBLKT, THREADS>>>(x, Wih_f, bih_f, bhh_f,
                                               Wih_b, bih_b, bhh_b);
    lstm_rec_kernel<<<128, 128>>>(Whh_f, Whh_b, out);
}